// round 16
// baseline (speedup 1.0000x reference)
#include <cuda_runtime.h>
#include <cuda_fp16.h>
#include <math.h>

#define BATCH 32
#define T     1024
#define DIM   64
#define NW    8                 // DP strips per batch (128 rows each)
#define NCH   76                // chunks of 16 steps: 1216 steps
#define SPAD  1248              // NCH*16 + 32 FIFO pad
#define HANDW 1232              // handoff row width (halves), 16B-aligned rows
#define SRMAX 221               // epilogue s-rows per tile
#define NUNITS 464              // producer units: 116 CTAs * 4
#define NTILES 8192             // 32 b * 8 w * 32 jt
#define PROG_OFF ((NW + 1) * HANDW * 2)       // 22176
// producer unit: Ah[128][72]h (reused as Ch[128][34]) | Bh[32][72]h | na[128]f | nb[32]f
#define BH_OFF     18432
#define NA_OFF     23040
#define NB_OFF     23552
#define UNIT_BYTES 24064
#define SMEM_DYN   (4 * UNIT_BYTES)           // 96256

// fp16 cost^2, skew-slotted: g_cst[((b*NW+w)*SPAD + s)*128 + i] holds
// cost[128w+i][s - phi(i)], phi(i) = 6*(i>>2) + (i&3). Invalid = +INF.
__device__ __half g_cst[(size_t)BATCH * NW * SPAD * 128];
__device__ float g_dists[BATCH];
__device__ int   g_done;
__device__ int   g_flag[BATCH * NW * 32];
__device__ unsigned char g_pairs[256];
__device__ unsigned char g_ihi[224];          // emit table: max i with phi(i)<=sr

__device__ __forceinline__ unsigned hmin2u(unsigned a, unsigned b) {
    __half2 r = __hmin2(*reinterpret_cast<__half2*>(&a), *reinterpret_cast<__half2*>(&b));
    return *reinterpret_cast<unsigned*>(&r);
}
__device__ __forceinline__ unsigned hmax2u(unsigned a, unsigned b) {
    __half2 r = __hmax2(*reinterpret_cast<__half2*>(&a), *reinterpret_cast<__half2*>(&b));
    return *reinterpret_cast<unsigned*>(&r);
}
__device__ __forceinline__ int ld_acq_gpu(const int* p) {
    int v; asm volatile("ld.acquire.gpu.s32 %0, [%1];" : "=r"(v) : "l"(p) : "memory");
    return v;
}

#define UBAR(id) asm volatile("bar.sync %0, %1;" :: "r"(id), "r"(128) : "memory")

#define LDMX4(r0, r1, r2, r3, addr)                                            \
    asm volatile("ldmatrix.sync.aligned.m8n8.x4.shared.b16 {%0,%1,%2,%3}, [%4];" \
                 : "=r"(r0), "=r"(r1), "=r"(r2), "=r"(r3) : "r"(addr))

#define MMA16816(c, a, bb0, bb1)                                               \
    asm volatile("mma.sync.aligned.m16n8k16.row.col.f32.f16.f16.f32 "          \
                 "{%0,%1,%2,%3},{%4,%5,%6,%7},{%8,%9},{%0,%1,%2,%3};"          \
                 : "+f"((c)[0]), "+f"((c)[1]), "+f"((c)[2]), "+f"((c)[3])      \
                 : "r"((a)[0]), "r"((a)[1]), "r"((a)[2]), "r"((a)[3]),         \
                   "r"(bb0), "r"(bb1))

// ---------------------------------------------------------------------------
// fill: INF boundary slots (512 CTAs, 2 per strip); zero flags; tables; g_done.
// ---------------------------------------------------------------------------
__global__ __launch_bounds__(256) void fill_kernel() {
    int cta = blockIdx.x;
    int strip = cta >> 1, half = cta & 1;
    unsigned* p32 = (unsigned*)(g_cst + (size_t)strip * SPAD * 128);
    const int NS = 189 + (SPAD - 1024);          // 413 slots
    int lo = half ? 207 : 0, hi = half ? NS : 207;
    for (int v = lo * 64 + threadIdx.x; v < hi * 64; v += 256) {
        int sr = v >> 6, q = v & 63;
        int s = (sr < 189) ? sr : (1024 + sr - 189);
        p32[(size_t)s * 64 + q] = 0x7C007C00u;
    }
    if (half == 0 && threadIdx.x < 32) g_flag[strip * 32 + threadIdx.x] = 0;
    if (cta == 0 && threadIdx.x == 0) {
        int idx = 0;
        for (int m = 0; m <= 80; m++)
            for (int w = 0; w < 8; w++) {
                int jt = m - 7 * w;
                if (jt >= 0 && jt < 32) g_pairs[idx++] = (unsigned char)(w * 32 + jt);
            }
        g_done = 0;
    }
    if (cta == 1 && threadIdx.x < 224) {
        int sr = threadIdx.x;
        int aq = sr / 6, bq = sr - 6 * aq;
        int ihi = 4 * aq + (bq < 3 ? bq : 3);
        g_ihi[sr] = (unsigned char)(ihi > 127 ? 127 : ihi);
    }
}

// ---------------------------------------------------------------------------
// Producer unit (unchanged from R15): fp16 tensor-core GEMM, 128x32 tile,
// priority tile order, release = bar + st.release.gpu.
// ---------------------------------------------------------------------------
__device__ void producer_part(const float* __restrict__ A, const float* __restrict__ B,
                              char* __restrict__ base, int barid, int unit, int t128) {
    __half* Ah  = (__half*)base;                 // [128][72]
    __half* Bh  = (__half*)(base + BH_OFF);      // [32][72]
    float* na_s = (float*)(base + NA_OFF);       // [128]
    float* nb_s = (float*)(base + NB_OFF);       // [32]
    const int wq = t128 >> 5, l = t128 & 31;
    const int r0 = t128 >> 4, kq = t128 & 15;
    const unsigned sBase = (unsigned)__cvta_generic_to_shared(base);
    const unsigned sAh = sBase, sBh = sBase + BH_OFF;

    const int m0 = 32 * wq;
    const unsigned ahAddr = sAh + (unsigned)(((m0 + (l & 15)) * 72 + (l >> 4) * 8) * 2);
    const unsigned bhAddr = sBh + (unsigned)((((l & 15)) * 72 + (l >> 4) * 8) * 2);

    for (int p = unit; p < NTILES; p += NUNITS) {
        int pr = g_pairs[p >> 5];
        int b = p & 31, w = pr >> 5, jt = pr & 31;
        int j0 = jt * 32;

        {
            const float4* Ar = (const float4*)(A + ((size_t)b * T + w * 128) * DIM);
#pragma unroll
            for (int it = 0; it < 16; it++) {
                int row = r0 + it * 8;
                float4 x = Ar[row * 16 + kq];
                float part = x.x * x.x + x.y * x.y + x.z * x.z + x.w * x.w;
                part += __shfl_xor_sync(0xffffffffu, part, 1);
                part += __shfl_xor_sync(0xffffffffu, part, 2);
                part += __shfl_xor_sync(0xffffffffu, part, 4);
                part += __shfl_xor_sync(0xffffffffu, part, 8);
                if (kq == 0) na_s[row] = part;
                __half2 h0 = __floats2half2_rn(x.x, x.y);
                __half2 h1 = __floats2half2_rn(x.z, x.w);
                uint2 u; u.x = *(unsigned*)&h0; u.y = *(unsigned*)&h1;
                *(uint2*)(Ah + row * 72 + kq * 4) = u;
            }
        }
        {
            const float4* Br = (const float4*)(B + ((size_t)b * T + j0) * DIM);
#pragma unroll
            for (int it = 0; it < 4; it++) {
                int row = r0 + it * 8;
                float4 x = Br[row * 16 + kq];
                float part = x.x * x.x + x.y * x.y + x.z * x.z + x.w * x.w;
                part += __shfl_xor_sync(0xffffffffu, part, 1);
                part += __shfl_xor_sync(0xffffffffu, part, 2);
                part += __shfl_xor_sync(0xffffffffu, part, 4);
                part += __shfl_xor_sync(0xffffffffu, part, 8);
                if (kq == 0) nb_s[row] = part;
                __half2 h0 = __floats2half2_rn(x.x, x.y);
                __half2 h1 = __floats2half2_rn(x.z, x.w);
                uint2 u; u.x = *(unsigned*)&h0; u.y = *(unsigned*)&h1;
                *(uint2*)(Bh + row * 72 + kq * 4) = u;
            }
        }
        UBAR(barid);

        float acc[2][4][4];
#pragma unroll
        for (int mi = 0; mi < 2; mi++)
#pragma unroll
            for (int nj = 0; nj < 4; nj++)
#pragma unroll
                for (int q = 0; q < 4; q++) acc[mi][nj][q] = 0.f;

#pragma unroll
        for (int kk = 0; kk < 4; kk++) {
            unsigned a0[4], a1[4], b0[4], b1[4];
            LDMX4(a0[0], a0[1], a0[2], a0[3], ahAddr + kk * 32);
            LDMX4(a1[0], a1[1], a1[2], a1[3], ahAddr + 2304 + kk * 32);
            LDMX4(b0[0], b0[1], b0[2], b0[3], bhAddr + kk * 32);
            LDMX4(b1[0], b1[1], b1[2], b1[3], bhAddr + 2304 + kk * 32);
            MMA16816(acc[0][0], a0, b0[0], b0[2]);
            MMA16816(acc[0][1], a0, b0[1], b0[3]);
            MMA16816(acc[0][2], a0, b1[0], b1[2]);
            MMA16816(acc[0][3], a0, b1[1], b1[3]);
            MMA16816(acc[1][0], a1, b0[0], b0[2]);
            MMA16816(acc[1][1], a1, b0[1], b0[3]);
            MMA16816(acc[1][2], a1, b1[0], b1[2]);
            MMA16816(acc[1][3], a1, b1[1], b1[3]);
        }
        UBAR(barid);                 // Ah reads done; reuse as Ch

        __half* Ch = (__half*)base;  // [128][34]
        {
            const int cb = 2 * (l & 3);
#pragma unroll
            for (int mi = 0; mi < 2; mi++) {
                int r = m0 + 16 * mi + (l >> 2);
                float na0 = na_s[r], na8 = na_s[r + 8];
#pragma unroll
                for (int nj = 0; nj < 4; nj++) {
                    int c0 = 8 * nj + cb;
                    float nb0 = nb_s[c0], nb1 = nb_s[c0 + 1];
                    float s00 = fmaxf(na0 + nb0 - 2.f * acc[mi][nj][0], 1e-12f);
                    float s01 = fmaxf(na0 + nb1 - 2.f * acc[mi][nj][1], 1e-12f);
                    float s10 = fmaxf(na8 + nb0 - 2.f * acc[mi][nj][2], 1e-12f);
                    float s11 = fmaxf(na8 + nb1 - 2.f * acc[mi][nj][3], 1e-12f);
                    __half2 h0 = __floats2half2_rn(s00, s01);
                    __half2 h1 = __floats2half2_rn(s10, s11);
                    *(unsigned*)&Ch[r * 34 + c0] = *(unsigned*)&h0;
                    *(unsigned*)&Ch[(r + 8) * 34 + c0] = *(unsigned*)&h1;
                }
            }
        }
        UBAR(barid);

        size_t sbase_g = ((size_t)(b * NW + w) * SPAD + j0) * 128;
#pragma unroll 4
        for (int it = 0; it < 56; it++) {
            int sr = it * 4 + wq;
            if (sr < SRMAX) {
                int ihi = __ldg(&g_ihi[sr]);
                int i = ihi - 31 + l;
                int jr = sr - (6 * (i >> 2) + (i & 3));
                if (i >= 0 && jr >= 0 && jr < 32)
                    g_cst[sbase_g + (size_t)sr * 128 + i] = Ch[i * 34 + jr];
            }
        }
        UBAR(barid);                 // hb: all emit STGs ordered before release
        if (t128 == 0)
            asm volatile("st.release.gpu.s32 [%0], %1;"
                         :: "l"(&g_flag[(b * NW + w) * 32 + jt]), "r"(1) : "memory");
    }
}

// ---------------------------------------------------------------------------
// DP part: E=2-skew systolic engine with BATCHED handoff:
//   hand[w][k] = strip-w bottom-row value for col (k-13).
//   Producer: 2 predicated STS.128 per 16 steps (pack via byte_perm).
//   Consumer: 3 LDS.128 per 16 steps, compile-time extraction.
// Per-step MIO drops from 4 to ~2 ops.
// ---------------------------------------------------------------------------
__device__ void dp_part(int b, char* smem, float* __restrict__ out) {
    unsigned short* hand = (unsigned short*)smem;
    int* progress = (int*)(smem + PROG_OFF);
    const int tid = threadIdx.x, w = tid >> 5, lane = tid & 31;

    for (int v = tid; v < (NW + 1) * HANDW / 2; v += 256)
        ((unsigned*)hand)[v] = 0x7C007C00u;
    if (lane == 0) progress[w] = 0;
    asm volatile("bar.sync 5, 256;" ::: "memory");

    unsigned handb;
    asm("{ .reg .u64 t; cvta.to.shared.u64 t, %1; cvt.u32.u64 %0, t; }"
        : "=r"(handb) : "l"(hand));
    const unsigned hrowb = handb + (unsigned)(((w == 0) ? NW : (w - 1)) * HANDW * 2);
    const unsigned wrowb = handb + (unsigned)(w * HANDW * 2);

    const int fbase = (b * NW + w) * 32;
    int done = 0;
    while (ld_acq_gpu(&g_flag[fbase]) == 0) __nanosleep(128);
    done = 1;

    const __half* cp = g_cst + (size_t)(b * NW + w) * SPAD * 128 + lane * 4;
    uint2 fA[16], fB[16];
#pragma unroll
    for (int q = 0; q < 16; q++) fA[q] = *(const uint2*)(cp + (size_t)q * 128);
#pragma unroll
    for (int q = 0; q < 16; q++) fB[q] = *(const uint2*)(cp + (size_t)(16 + q) * 128);

    const unsigned INF2 = 0x7C007C00u;
    unsigned A = INF2, B = INF2, upAp = INF2, upBp = INF2;
    unsigned sh0 = INF2, sh1 = INF2;
    const bool isl0 = (lane == 0);
    const bool fix0 = (w == 0) && isl0;
    const unsigned p31 = (lane == 31) ? 1u : 0u;
    const __half* cq = cp;

// load 3 aligned uint4 of hand: covers hand idx sbase+8 .. sbase+31
#define LDH3(hq, sb)                                                           \
    {                                                                          \
        unsigned _a = hrowb + (unsigned)((sb) * 2) + 16u;                      \
        asm volatile("ld.shared.v4.u32 {%0,%1,%2,%3}, [%4];"                   \
            : "=r"(hq[0]), "=r"(hq[1]), "=r"(hq[2]), "=r"(hq[3]) : "r"(_a));   \
        asm volatile("ld.shared.v4.u32 {%0,%1,%2,%3}, [%4];"                   \
            : "=r"(hq[4]), "=r"(hq[5]), "=r"(hq[6]), "=r"(hq[7]) : "r"(_a + 16u)); \
        asm volatile("ld.shared.v4.u32 {%0,%1,%2,%3}, [%4];"                   \
            : "=r"(hq[8]), "=r"(hq[9]), "=r"(hq[10]), "=r"(hq[11]) : "r"(_a + 32u)); \
    }

// batched publish: 16 u16 (steps sbase..sbase+15) at hand idx sbase-176..+15
#define STH2(pk, sb)                                                           \
    {                                                                          \
        unsigned _pr = p31 & (unsigned)((sb) >= 176);                          \
        unsigned _wa = wrowb + (unsigned)((sb) * 2) - 352u;                    \
        asm volatile("{ .reg .pred p; setp.ne.u32 p, %0, 0;\n\t"               \
            "@p st.shared.v4.b32 [%1], {%2,%3,%4,%5};\n\t"                     \
            "@p st.shared.v4.b32 [%1+16], {%6,%7,%8,%9}; }"                    \
            :: "r"(_pr), "r"(_wa), "r"(pk[0]), "r"(pk[1]), "r"(pk[2]),         \
               "r"(pk[3]), "r"(pk[4]), "r"(pk[5]), "r"(pk[6]), "r"(pk[7]));    \
    }

// hand value for step sbase+kk: idx sbase+kk+13, offset from load base = kk+5
#define DP_STEP(kk, F, ROFF, FIRST)                                            \
    {                                                                          \
        uint2 cw = F[kk];                                                      \
        F[kk] = *(const uint2*)(cq + (size_t)((kk) + (ROFF)) * 128);           \
        unsigned hw = hq[((kk) + 5) >> 1];                                     \
        unsigned hvp = (((kk) + 5) & 1) ? (hw & 0xFFFF0000u) : (hw << 16);     \
        unsigned shu = isl0 ? hvp : sh0;                                       \
        unsigned upA = __byte_perm(shu, A, 0x5432);                            \
        unsigned upB = __byte_perm(A, B, 0x5432);                              \
        unsigned nA = hmax2u(cw.x, hmin2u(hmin2u(upA, upAp), A));              \
        unsigned nB = hmax2u(cw.y, hmin2u(hmin2u(upB, upBp), B));              \
        if ((FIRST) && (kk) == 0) {                                            \
            if (fix0) nA = (nA & 0xFFFF0000u) | (cw.x & 0xFFFFu);              \
        }                                                                      \
        if ((kk) & 1) pk[(kk) >> 1] = __byte_perm(nBsav, nB, 0x7632);          \
        else nBsav = nB;                                                       \
        unsigned shn = __shfl_up_sync(0xffffffffu, B, 1);                      \
        sh0 = sh1; sh1 = shn;                                                  \
        upAp = upA; upBp = upB;                                                \
        A = nA; B = nB;                                                        \
    }

    for (int td = 0; td < NCH / 2; td++) {
        {   // gate: chunk td refills read slots <= 32*td+63 -> tiles <= td+1
            int need = td + 2; if (need > 32) need = 32;
            while (done < need) {
                if (ld_acq_gpu(&g_flag[fbase + done]) != 0) done++;
                else __nanosleep(64);
            }
        }
        if (w) {
            int need = 2 * td + 14; if (need > NCH) need = NCH;
            while (((volatile int*)progress)[w - 1] < need) __nanosleep(32);
            __threadfence_block();
        }
        {
            const int sbase = 32 * td;
            unsigned hq[12], pk[8], nBsav;
            LDH3(hq, sbase)
#pragma unroll
            for (int kk = 0; kk < 16; kk++) DP_STEP(kk, fA, 32, (td == 0))
            STH2(pk, sbase)
        }
        __syncwarp();
        __threadfence_block();
        if (lane == 0) ((volatile int*)progress)[w] = 2 * td + 1;
        {
            const int sbase = 32 * td + 16;
            unsigned hq[12], pk[8], nBsav;
            LDH3(hq, sbase)
#pragma unroll
            for (int kk = 0; kk < 16; kk++) DP_STEP(kk, fB, 48, false)
            STH2(pk, sbase)
        }
        __syncwarp();
        __threadfence_block();
        if (lane == 0) ((volatile int*)progress)[w] = 2 * td + 2;
        cq += 32 * 128;
    }
#undef DP_STEP
#undef LDH3
#undef STH2

    asm volatile("bar.sync 5, 256;" ::: "memory");
    if (tid == 0) {
        // col 1023 lives at hand idx 1023+13
        g_dists[b] = sqrtf(__half2float(__ushort_as_half(hand[7 * HANDW + 1036])));
        __threadfence();
        int old = atomicAdd(&g_done, 1);
        if (old == BATCH - 1) {                    // last CTA reduces (merged finish)
            __threadfence();
            float s = 0.f;
#pragma unroll
            for (int i = 0; i < BATCH; i++) s += ((volatile float*)g_dists)[i];
            out[0] = s * (1.0f / BATCH);
        }
    }
}

// ---------------------------------------------------------------------------
// Fused persistent kernel, 148 CTAs (all wave-1 resident), 512 threads.
//   CTA 0..31:  DP warps only (batch = blockIdx; tids 256+ exit).
//   CTA 32..147: 4 tensor-core producer units each (464 total).
// ---------------------------------------------------------------------------
__global__ void __launch_bounds__(512, 1) fused_kernel(const float* __restrict__ A,
                                                       const float* __restrict__ B,
                                                       float* __restrict__ out) {
    extern __shared__ char smem[];
    const int cta = blockIdx.x, tid = threadIdx.x;
    if (cta < BATCH) {
        if (tid < 256) dp_part(cta, smem, out);
        return;
    }
    int ul = tid >> 7;
    producer_part(A, B, smem + ul * UNIT_BYTES, 1 + ul,
                  (cta - BATCH) * 4 + ul, tid & 127);
}

extern "C" void kernel_launch(void* const* d_in, const int* in_sizes, int n_in,
                              void* d_out, int out_size) {
    const float* pred = (const float*)d_in[0];
    const float* targ = (const float*)d_in[1];
    cudaFuncSetAttribute(fused_kernel, cudaFuncAttributeMaxDynamicSharedMemorySize, SMEM_DYN);
    fill_kernel<<<512, 256>>>();
    fused_kernel<<<148, 512, SMEM_DYN>>>(pred, targ, (float*)d_out);
}